// round 3
// baseline (speedup 1.0000x reference)
#include <cuda_runtime.h>
#include <cuda_bf16.h>

// Elementwise clip: out = min(max(x, lo), hi)
// x: 33,554,432 fp32 = 8,388,608 float4s = 4096 blocks x 256 threads x 8 float4s (exact).
// Fast path: no bounds checks (exact division), 8 front-batched streaming LDG.128,
// streaming STG.128 (zero L2 reuse on a 268MB sweep). Guarded fallback otherwise.

#define VPT 8

__global__ __launch_bounds__(256) void clip_kernel_v4x8_exact(
    const float4* __restrict__ x,
    const float* __restrict__ clamp_params,
    float4* __restrict__ out)
{
    const float lo = clamp_params[0];
    const float hi = clamp_params[1];

    int base = blockIdx.x * (256 * VPT) + threadIdx.x;

    float4 v[VPT];
    #pragma unroll
    for (int k = 0; k < VPT; k++)
        v[k] = __ldcs(&x[base + k * 256]);

    #pragma unroll
    for (int k = 0; k < VPT; k++) {
        v[k].x = fminf(fmaxf(v[k].x, lo), hi);
        v[k].y = fminf(fmaxf(v[k].y, lo), hi);
        v[k].z = fminf(fmaxf(v[k].z, lo), hi);
        v[k].w = fminf(fmaxf(v[k].w, lo), hi);
    }

    #pragma unroll
    for (int k = 0; k < VPT; k++)
        __stcs(&out[base + k * 256], v[k]);
}

// Generic fallback (any size), float4 + scalar tail via grid-stride on floats.
__global__ __launch_bounds__(256) void clip_kernel_generic(
    const float* __restrict__ x,
    const float* __restrict__ clamp_params,
    float* __restrict__ out,
    int n)
{
    const float lo = clamp_params[0];
    const float hi = clamp_params[1];
    for (int i = blockIdx.x * blockDim.x + threadIdx.x; i < n;
         i += gridDim.x * blockDim.x)
        out[i] = fminf(fmaxf(__ldcs(&x[i]), lo), hi);
}

extern "C" void kernel_launch(void* const* d_in, const int* in_sizes, int n_in,
                              void* d_out, int out_size)
{
    const float* x = (const float*)d_in[0];
    const float* clamp_params = (const float*)d_in[1];
    float* out = (float*)d_out;

    int n = out_size;          // 33,554,432
    const int threads = 256;
    const int chunk = threads * VPT * 4;  // floats covered per block: 8192

    if ((n % chunk) == 0) {
        int blocks = n / chunk;  // 4096
        clip_kernel_v4x8_exact<<<blocks, threads>>>(
            (const float4*)x, clamp_params, (float4*)out);
    } else {
        int blocks = (n + threads - 1) / threads;
        if (blocks > 65535 * 16) blocks = 65535 * 16;
        clip_kernel_generic<<<blocks, threads>>>(x, clamp_params, out, n);
    }
}

// round 4
// speedup vs baseline: 1.0471x; 1.0471x over previous
#include <cuda_runtime.h>
#include <cuda_bf16.h>

// Elementwise clip: out = min(max(x, lo), hi)
// x: 33,554,432 fp32 = 8,388,608 float4s = 8192 blocks x 256 threads x 4 float4s (exact).
// R1 config (best: 35.6us, DRAM 75.9%) minus bounds predicates.
// VPT=4 keeps regs low (occupancy ~78%) while giving 4 front-batched LDG.128/thread;
// streaming hints since the 268MB sweep has zero L2 reuse.

#define VPT 4

__global__ __launch_bounds__(256) void clip_kernel_v4x4_exact(
    const float4* __restrict__ x,
    const float* __restrict__ clamp_params,
    float4* __restrict__ out)
{
    const float lo = clamp_params[0];
    const float hi = clamp_params[1];

    int base = blockIdx.x * (256 * VPT) + threadIdx.x;

    float4 v[VPT];
    #pragma unroll
    for (int k = 0; k < VPT; k++)
        v[k] = __ldcs(&x[base + k * 256]);

    #pragma unroll
    for (int k = 0; k < VPT; k++) {
        v[k].x = fminf(fmaxf(v[k].x, lo), hi);
        v[k].y = fminf(fmaxf(v[k].y, lo), hi);
        v[k].z = fminf(fmaxf(v[k].z, lo), hi);
        v[k].w = fminf(fmaxf(v[k].w, lo), hi);
    }

    #pragma unroll
    for (int k = 0; k < VPT; k++)
        __stcs(&out[base + k * 256], v[k]);
}

// Generic fallback (any size).
__global__ __launch_bounds__(256) void clip_kernel_generic(
    const float* __restrict__ x,
    const float* __restrict__ clamp_params,
    float* __restrict__ out,
    int n)
{
    const float lo = clamp_params[0];
    const float hi = clamp_params[1];
    for (int i = blockIdx.x * blockDim.x + threadIdx.x; i < n;
         i += gridDim.x * blockDim.x)
        out[i] = fminf(fmaxf(__ldcs(&x[i]), lo), hi);
}

extern "C" void kernel_launch(void* const* d_in, const int* in_sizes, int n_in,
                              void* d_out, int out_size)
{
    const float* x = (const float*)d_in[0];
    const float* clamp_params = (const float*)d_in[1];
    float* out = (float*)d_out;

    int n = out_size;          // 33,554,432
    const int threads = 256;
    const int chunk = threads * VPT * 4;  // floats per block: 4096

    if ((n % chunk) == 0) {
        int blocks = n / chunk;  // 8192
        clip_kernel_v4x4_exact<<<blocks, threads>>>(
            (const float4*)x, clamp_params, (float4*)out);
    } else {
        int blocks = (n + threads - 1) / threads;
        if (blocks > 65535 * 16) blocks = 65535 * 16;
        clip_kernel_generic<<<blocks, threads>>>(x, clamp_params, out, n);
    }
}